// round 1
// baseline (speedup 1.0000x reference)
#include <cuda_runtime.h>
#include <cstdint>

// Problem constants (fixed by the dataset)
#define B_   16
#define S_   2048
#define D_   1024
#define P_   8192
#define R_   16
#define NL_  64

#define NCH  16            // chunks along sequence
#define CHL  (S_ / NCH)    // 128 rows per chunk
#define OUTW (2 * D_ + R_) // 2064 floats per output row

// Scratch: exclusive prefix sums cs[b][s][d], s in [0..S] (row s holds sum of first s tokens)
__device__ float g_cs[(size_t)B_ * (S_ + 1) * D_];        // ~134 MB
__device__ float g_part[(size_t)B_ * NCH * D_];           // chunk partial sums -> exclusive bases

// ---------------------------------------------------------------------------
// Pass 1: per-(b, chunk, d4) partial sums over CHL rows. float4 vectorized.
// threads = B*NCH*(D/4) = 65536
__global__ void pass1_partials(const float* __restrict__ tok) {
    int idx = blockIdx.x * blockDim.x + threadIdx.x;     // [0, 65536)
    int d4   = idx & (D_ / 4 - 1);
    int rest = idx >> 8;                                  // D/4 = 256
    int ch   = rest & (NCH - 1);
    int b    = rest >> 4;

    const float4* t = (const float4*)(tok + ((size_t)b * S_ + (size_t)ch * CHL) * D_) + d4;
    float4 acc = make_float4(0.f, 0.f, 0.f, 0.f);
#pragma unroll 8
    for (int s = 0; s < CHL; ++s) {
        float4 v = t[(size_t)s * (D_ / 4)];
        acc.x += v.x; acc.y += v.y; acc.z += v.z; acc.w += v.w;
    }
    ((float4*)(g_part + ((size_t)b * NCH + ch) * D_))[d4] = acc;
}

// ---------------------------------------------------------------------------
// Pass 2: exclusive scan of the NCH chunk partials per (b, d4), in place.
// threads = B*(D/4) = 4096
__global__ void pass2_scan() {
    int idx = blockIdx.x * blockDim.x + threadIdx.x;     // [0, 4096)
    int d4 = idx & (D_ / 4 - 1);
    int b  = idx >> 8;

    float4 run = make_float4(0.f, 0.f, 0.f, 0.f);
    for (int ch = 0; ch < NCH; ++ch) {
        float4* p = (float4*)(g_part + ((size_t)b * NCH + ch) * D_) + d4;
        float4 v = *p;
        *p = run;
        run.x += v.x; run.y += v.y; run.z += v.z; run.w += v.w;
    }
}

// ---------------------------------------------------------------------------
// Pass 3: emit cs rows. Same decomposition as pass 1.
__global__ void pass3_emit(const float* __restrict__ tok) {
    int idx = blockIdx.x * blockDim.x + threadIdx.x;
    int d4   = idx & (D_ / 4 - 1);
    int rest = idx >> 8;
    int ch   = rest & (NCH - 1);
    int b    = rest >> 4;

    const float4* t = (const float4*)(tok + ((size_t)b * S_ + (size_t)ch * CHL) * D_) + d4;
    float4* cs = (float4*)(g_cs + (size_t)b * (S_ + 1) * D_) + d4;

    float4 run = ((const float4*)(g_part + ((size_t)b * NCH + ch) * D_))[d4];
    if (ch == 0) cs[0] = make_float4(0.f, 0.f, 0.f, 0.f);

    int row0 = ch * CHL + 1;   // cs row index for first emitted sum
#pragma unroll 4
    for (int s = 0; s < CHL; ++s) {
        float4 v = t[(size_t)s * (D_ / 4)];
        run.x += v.x; run.y += v.y; run.z += v.z; run.w += v.w;
        cs[(size_t)(row0 + s) * (D_ / 4)] = run;
    }
}

// ---------------------------------------------------------------------------
// Pass 4: one block per pair. 256 threads, each handles one float4 lane (D/4=256).
__global__ void pass4_pairs(const int* __restrict__ batch_idx,
                            const int* __restrict__ e1s, const int* __restrict__ e1e,
                            const int* __restrict__ e2s, const int* __restrict__ e2e,
                            const int* __restrict__ rel_idx,
                            const float* __restrict__ rel_table,
                            float* __restrict__ out) {
    int p = blockIdx.x;
    int t = threadIdx.x;                // 0..255 = float4 lane

    int b  = __ldg(batch_idx + p);
    int s1 = __ldg(e1s + p), f1 = __ldg(e1e + p);
    int s2 = __ldg(e2s + p), f2 = __ldg(e2e + p);

    const float4* cs = (const float4*)(g_cs + (size_t)b * (S_ + 1) * D_);
    float4* orow = (float4*)(out + (size_t)p * OUTW);

    float inv1 = 1.0f / (float)(f1 - s1);
    float inv2 = 1.0f / (float)(f2 - s2);

    float4 a = cs[(size_t)f1 * (D_ / 4) + t];
    float4 c = cs[(size_t)s1 * (D_ / 4) + t];
    float4 m1 = make_float4((a.x - c.x) * inv1, (a.y - c.y) * inv1,
                            (a.z - c.z) * inv1, (a.w - c.w) * inv1);
    orow[t] = m1;

    float4 e = cs[(size_t)f2 * (D_ / 4) + t];
    float4 g = cs[(size_t)s2 * (D_ / 4) + t];
    float4 m2 = make_float4((e.x - g.x) * inv2, (e.y - g.y) * inv2,
                            (e.z - g.z) * inv2, (e.w - g.w) * inv2);
    orow[D_ / 4 + t] = m2;

    if (t < R_) {
        int ri = __ldg(rel_idx + p);
        out[(size_t)p * OUTW + 2 * D_ + t] = __ldg(rel_table + (size_t)ri * R_ + t);
    }
}

// ---------------------------------------------------------------------------
extern "C" void kernel_launch(void* const* d_in, const int* in_sizes, int n_in,
                              void* d_out, int out_size) {
    const float* tok       = (const float*)d_in[0];
    const int*   batch_idx = (const int*)d_in[1];
    const int*   e1s       = (const int*)d_in[2];
    const int*   e1e       = (const int*)d_in[3];
    const int*   e2s       = (const int*)d_in[4];
    const int*   e2e       = (const int*)d_in[5];
    const int*   rel_idx   = (const int*)d_in[6];
    const float* rel_table = (const float*)d_in[7];
    float* out = (float*)d_out;

    (void)in_sizes; (void)n_in; (void)out_size;

    pass1_partials<<<B_ * NCH * (D_ / 4) / 256, 256>>>(tok);
    pass2_scan<<<B_ * (D_ / 4) / 256, 256>>>();
    pass3_emit<<<B_ * NCH * (D_ / 4) / 256, 256>>>(tok);
    pass4_pairs<<<P_, 256>>>(batch_idx, e1s, e1e, e2s, e2e, rel_idx, rel_table, out);
}

// round 2
// speedup vs baseline: 1.1349x; 1.1349x over previous
#include <cuda_runtime.h>
#include <cstdint>

// Problem constants (fixed by the dataset)
#define B_   16
#define S_   2048
#define D_   1024
#define P_   8192
#define R_   16

#define LCH  32               // rows per chunk
#define NCH  (S_ / LCH)       // 64 chunks
#define OUTW (2 * D_ + R_)    // 2064 floats per output row

// arr[b][s][d]: inclusive prefix of tok within the chunk containing s (only flagged rows valid)
__device__ float g_arr[(size_t)B_ * S_ * D_];            // ~134 MB
__device__ float g_part[(size_t)B_ * NCH * D_];          // chunk totals (4 MB)
__device__ float g_base[(size_t)B_ * NCH * D_];          // exclusive chunk bases (4 MB)
__device__ int   g_flag[(B_ * S_) / 4];                  // packed byte flags (8K ints)

// ---------------------------------------------------------------------------
// Zero the flag array (device globals persist across graph replays).
__global__ void k_init_flags() {
    int i = blockIdx.x * blockDim.x + threadIdx.x;
    if (i < (B_ * S_) / 4) g_flag[i] = 0;
}

// Mark rows of arr that pass4 will read: for endpoint e>0, row (e-1) of batch b.
__global__ void k_mark(const int* __restrict__ batch_idx,
                       const int* __restrict__ e1s, const int* __restrict__ e1e,
                       const int* __restrict__ e2s, const int* __restrict__ e2e) {
    int i = blockIdx.x * blockDim.x + threadIdx.x;      // [0, 4P)
    if (i >= 4 * P_) return;
    int p = i & (P_ - 1);
    int which = i >> 13;                                 // P = 8192 = 2^13
    int e;
    switch (which) {
        case 0: e = e1s[p]; break;
        case 1: e = e1e[p]; break;
        case 2: e = e2s[p]; break;
        default: e = e2e[p]; break;
    }
    if (e > 0) ((unsigned char*)g_flag)[batch_idx[p] * S_ + (e - 1)] = 1;
}

// ---------------------------------------------------------------------------
// Single tok pass: per (b, chunk, d4) running prefix; write only flagged rows;
// emit chunk total unconditionally.
__global__ void k_local_prefix(const float* __restrict__ tok) {
    __shared__ unsigned char sflag[LCH];
    int idx = blockIdx.x * blockDim.x + threadIdx.x;
    int d4   = idx & (D_ / 4 - 1);
    int rest = idx >> 8;                                  // D/4 = 256
    int ch   = rest & (NCH - 1);
    int b    = rest >> 6;                                 // NCH = 64

    if (threadIdx.x < LCH)
        sflag[threadIdx.x] = ((const unsigned char*)g_flag)[b * S_ + ch * LCH + threadIdx.x];
    __syncthreads();

    const float4* t  = (const float4*)(tok   + ((size_t)b * S_ + (size_t)ch * LCH) * D_) + d4;
    float4*       ar = (float4*)      (g_arr + ((size_t)b * S_ + (size_t)ch * LCH) * D_) + d4;

    float4 run = make_float4(0.f, 0.f, 0.f, 0.f);
#pragma unroll
    for (int i = 0; i < LCH; ++i) {
        float4 v = t[(size_t)i * (D_ / 4)];
        run.x += v.x; run.y += v.y; run.z += v.z; run.w += v.w;
        if (sflag[i]) ar[(size_t)i * (D_ / 4)] = run;
    }
    ((float4*)(g_part + ((size_t)b * NCH + ch) * D_))[d4] = run;
}

// ---------------------------------------------------------------------------
// Exclusive scan of chunk totals per (b, d4): base[b][c] = sum of chunks < c.
__global__ void k_scan_bases() {
    int idx = blockIdx.x * blockDim.x + threadIdx.x;     // [0, 4096)
    int d4 = idx & (D_ / 4 - 1);
    int b  = idx >> 8;

    float4 run = make_float4(0.f, 0.f, 0.f, 0.f);
#pragma unroll 8
    for (int c = 0; c < NCH; ++c) {
        ((float4*)(g_base + ((size_t)b * NCH + c) * D_))[d4] = run;
        float4 v = ((const float4*)(g_part + ((size_t)b * NCH + c) * D_))[d4];
        run.x += v.x; run.y += v.y; run.z += v.z; run.w += v.w;
    }
}

// ---------------------------------------------------------------------------
// One block per pair; 256 threads = float4 lanes. cs[e] = base[(e-1)/LCH] + arr[e-1].
__device__ __forceinline__ float4 cs_val(const float4* arr_b, const float4* base_b,
                                         int e, int t) {
    if (e == 0) return make_float4(0.f, 0.f, 0.f, 0.f);
    int cb = (e - 1) / LCH;
    float4 a  = arr_b [(size_t)(e - 1) * (D_ / 4) + t];
    float4 bs = base_b[(size_t)cb      * (D_ / 4) + t];
    return make_float4(a.x + bs.x, a.y + bs.y, a.z + bs.z, a.w + bs.w);
}

__global__ void k_pairs(const int* __restrict__ batch_idx,
                        const int* __restrict__ e1s, const int* __restrict__ e1e,
                        const int* __restrict__ e2s, const int* __restrict__ e2e,
                        const int* __restrict__ rel_idx,
                        const float* __restrict__ rel_table,
                        float* __restrict__ out) {
    int p = blockIdx.x;
    int t = threadIdx.x;

    int b  = __ldg(batch_idx + p);
    int s1 = __ldg(e1s + p), f1 = __ldg(e1e + p);
    int s2 = __ldg(e2s + p), f2 = __ldg(e2e + p);

    const float4* arr_b  = (const float4*)(g_arr  + (size_t)b * S_ * D_);
    const float4* base_b = (const float4*)(g_base + (size_t)b * NCH * D_);
    float4* orow = (float4*)(out + (size_t)p * OUTW);

    float inv1 = 1.0f / (float)(f1 - s1);
    float inv2 = 1.0f / (float)(f2 - s2);

    float4 a = cs_val(arr_b, base_b, f1, t);
    float4 c = cs_val(arr_b, base_b, s1, t);
    orow[t] = make_float4((a.x - c.x) * inv1, (a.y - c.y) * inv1,
                          (a.z - c.z) * inv1, (a.w - c.w) * inv1);

    float4 e = cs_val(arr_b, base_b, f2, t);
    float4 g = cs_val(arr_b, base_b, s2, t);
    orow[D_ / 4 + t] = make_float4((e.x - g.x) * inv2, (e.y - g.y) * inv2,
                                   (e.z - g.z) * inv2, (e.w - g.w) * inv2);

    if (t < R_) {
        int ri = __ldg(rel_idx + p);
        out[(size_t)p * OUTW + 2 * D_ + t] = __ldg(rel_table + (size_t)ri * R_ + t);
    }
}

// ---------------------------------------------------------------------------
extern "C" void kernel_launch(void* const* d_in, const int* in_sizes, int n_in,
                              void* d_out, int out_size) {
    const float* tok       = (const float*)d_in[0];
    const int*   batch_idx = (const int*)d_in[1];
    const int*   e1s       = (const int*)d_in[2];
    const int*   e1e       = (const int*)d_in[3];
    const int*   e2s       = (const int*)d_in[4];
    const int*   e2e       = (const int*)d_in[5];
    const int*   rel_idx   = (const int*)d_in[6];
    const float* rel_table = (const float*)d_in[7];
    float* out = (float*)d_out;

    (void)in_sizes; (void)n_in; (void)out_size;

    k_init_flags<<<(B_ * S_ / 4 + 255) / 256, 256>>>();
    k_mark<<<(4 * P_) / 256, 256>>>(batch_idx, e1s, e1e, e2s, e2e);
    k_local_prefix<<<B_ * NCH * (D_ / 4) / 256, 256>>>(tok);
    k_scan_bases<<<B_ * (D_ / 4) / 256, 256>>>();
    k_pairs<<<P_, 256>>>(batch_idx, e1s, e1e, e2s, e2e, rel_idx, rel_table, out);
}

// round 3
// speedup vs baseline: 1.2381x; 1.0910x over previous
#include <cuda_runtime.h>
#include <cstdint>

// Problem constants (fixed by the dataset)
#define B_   16
#define S_   2048
#define D_   1024
#define P_   8192
#define R_   16

#define LCH  32               // rows per chunk
#define NCH  (S_ / LCH)       // 64 chunks
#define OUTW (2 * D_ + R_)    // 2064 floats per output row

#define SCAN_TILE 8           // chunks staged in smem per scan iteration

// arr[b][s][d]: inclusive prefix of tok within the chunk containing s (only flagged rows valid)
__device__ float g_arr[(size_t)B_ * S_ * D_];            // ~134 MB
__device__ float g_part[(size_t)B_ * NCH * D_];          // chunk totals (4 MB)
__device__ float g_base[(size_t)B_ * NCH * D_];          // exclusive chunk bases (4 MB)
__device__ int   g_flag[(B_ * S_) / 4];                  // packed byte flags (8K ints)

// ---------------------------------------------------------------------------
// Zero the flag array (device globals persist across graph replays).
__global__ void k_init_flags() {
    int i = blockIdx.x * blockDim.x + threadIdx.x;
    if (i < (B_ * S_) / 4) g_flag[i] = 0;
}

// Mark rows of arr that pairs will read: for endpoint e>0, row (e-1) of batch b.
__global__ void k_mark(const int* __restrict__ batch_idx,
                       const int* __restrict__ e1s, const int* __restrict__ e1e,
                       const int* __restrict__ e2s, const int* __restrict__ e2e) {
    int i = blockIdx.x * blockDim.x + threadIdx.x;      // [0, 4P)
    if (i >= 4 * P_) return;
    int p = i & (P_ - 1);
    int which = i >> 13;                                 // P = 8192 = 2^13
    int e;
    switch (which) {
        case 0: e = e1s[p]; break;
        case 1: e = e1e[p]; break;
        case 2: e = e2s[p]; break;
        default: e = e2e[p]; break;
    }
    if (e > 0) ((unsigned char*)g_flag)[batch_idx[p] * S_ + (e - 1)] = 1;
}

// ---------------------------------------------------------------------------
// Single tok pass: per (b, chunk, d4) running prefix; write only flagged rows;
// emit chunk total unconditionally.
__global__ void k_local_prefix(const float* __restrict__ tok) {
    __shared__ unsigned char sflag[LCH];
    int idx = blockIdx.x * blockDim.x + threadIdx.x;
    int d4   = idx & (D_ / 4 - 1);
    int rest = idx >> 8;                                  // D/4 = 256
    int ch   = rest & (NCH - 1);
    int b    = rest >> 6;                                 // NCH = 64

    if (threadIdx.x < LCH)
        sflag[threadIdx.x] = ((const unsigned char*)g_flag)[b * S_ + ch * LCH + threadIdx.x];
    __syncthreads();

    const float4* t  = (const float4*)(tok   + ((size_t)b * S_ + (size_t)ch * LCH) * D_) + d4;
    float4*       ar = (float4*)      (g_arr + ((size_t)b * S_ + (size_t)ch * LCH) * D_) + d4;

    float4 run = make_float4(0.f, 0.f, 0.f, 0.f);
#pragma unroll
    for (int i = 0; i < LCH; ++i) {
        float4 v = t[(size_t)i * (D_ / 4)];
        run.x += v.x; run.y += v.y; run.z += v.z; run.w += v.w;
        if (sflag[i]) ar[(size_t)i * (D_ / 4)] = run;
    }
    ((float4*)(g_part + ((size_t)b * NCH + ch) * D_))[d4] = run;
}

// ---------------------------------------------------------------------------
// Exclusive scan of chunk totals per (b, d4), smem-staged for memory-level
// parallelism: one block per batch, 256 threads = d4 lanes, chunks in tiles.
__global__ void k_scan_bases() {
    __shared__ float4 tile[SCAN_TILE][D_ / 4];
    int b = blockIdx.x;
    int t = threadIdx.x;

    const float4* part = (const float4*)(g_part + (size_t)b * NCH * D_);
    float4*       base = (float4*)      (g_base + (size_t)b * NCH * D_);

    float4 run = make_float4(0.f, 0.f, 0.f, 0.f);
    for (int c0 = 0; c0 < NCH; c0 += SCAN_TILE) {
        __syncthreads();
#pragma unroll
        for (int i = 0; i < SCAN_TILE; ++i)
            tile[i][t] = part[(size_t)(c0 + i) * (D_ / 4) + t];
        __syncthreads();
#pragma unroll
        for (int i = 0; i < SCAN_TILE; ++i) {
            base[(size_t)(c0 + i) * (D_ / 4) + t] = run;
            float4 v = tile[i][t];
            run.x += v.x; run.y += v.y; run.z += v.z; run.w += v.w;
        }
    }
}

// ---------------------------------------------------------------------------
// One block per pair; 256 threads = float4 lanes. cs[e] = base[(e-1)/LCH] + arr[e-1].
__device__ __forceinline__ float4 cs_val(const float4* arr_b, const float4* base_b,
                                         int e, int t) {
    if (e == 0) return make_float4(0.f, 0.f, 0.f, 0.f);
    int cb = (e - 1) / LCH;
    float4 a  = arr_b [(size_t)(e - 1) * (D_ / 4) + t];
    float4 bs = base_b[(size_t)cb      * (D_ / 4) + t];
    return make_float4(a.x + bs.x, a.y + bs.y, a.z + bs.z, a.w + bs.w);
}

__global__ void k_pairs(const int* __restrict__ batch_idx,
                        const int* __restrict__ e1s, const int* __restrict__ e1e,
                        const int* __restrict__ e2s, const int* __restrict__ e2e,
                        const int* __restrict__ rel_idx,
                        const float* __restrict__ rel_table,
                        float* __restrict__ out) {
    int p = blockIdx.x;
    int t = threadIdx.x;

    int b  = __ldg(batch_idx + p);
    int s1 = __ldg(e1s + p), f1 = __ldg(e1e + p);
    int s2 = __ldg(e2s + p), f2 = __ldg(e2e + p);

    const float4* arr_b  = (const float4*)(g_arr  + (size_t)b * S_ * D_);
    const float4* base_b = (const float4*)(g_base + (size_t)b * NCH * D_);
    float4* orow = (float4*)(out + (size_t)p * OUTW);

    float inv1 = 1.0f / (float)(f1 - s1);
    float inv2 = 1.0f / (float)(f2 - s2);

    float4 a = cs_val(arr_b, base_b, f1, t);
    float4 c = cs_val(arr_b, base_b, s1, t);
    orow[t] = make_float4((a.x - c.x) * inv1, (a.y - c.y) * inv1,
                          (a.z - c.z) * inv1, (a.w - c.w) * inv1);

    float4 e = cs_val(arr_b, base_b, f2, t);
    float4 g = cs_val(arr_b, base_b, s2, t);
    orow[D_ / 4 + t] = make_float4((e.x - g.x) * inv2, (e.y - g.y) * inv2,
                                   (e.z - g.z) * inv2, (e.w - g.w) * inv2);

    if (t < R_) {
        int ri = __ldg(rel_idx + p);
        out[(size_t)p * OUTW + 2 * D_ + t] = __ldg(rel_table + (size_t)ri * R_ + t);
    }
}

// ---------------------------------------------------------------------------
extern "C" void kernel_launch(void* const* d_in, const int* in_sizes, int n_in,
                              void* d_out, int out_size) {
    const float* tok       = (const float*)d_in[0];
    const int*   batch_idx = (const int*)d_in[1];
    const int*   e1s       = (const int*)d_in[2];
    const int*   e1e       = (const int*)d_in[3];
    const int*   e2s       = (const int*)d_in[4];
    const int*   e2e       = (const int*)d_in[5];
    const int*   rel_idx   = (const int*)d_in[6];
    const float* rel_table = (const float*)d_in[7];
    float* out = (float*)d_out;

    (void)in_sizes; (void)n_in; (void)out_size;

    k_init_flags<<<(B_ * S_ / 4 + 255) / 256, 256>>>();
    k_mark<<<(4 * P_) / 256, 256>>>(batch_idx, e1s, e1e, e2s, e2e);
    k_local_prefix<<<B_ * NCH * (D_ / 4) / 256, 256>>>(tok);
    k_scan_bases<<<B_, 256>>>();
    k_pairs<<<P_, 256>>>(batch_idx, e1s, e1e, e2s, e2e, rel_idx, rel_table, out);
}

// round 4
// speedup vs baseline: 1.3220x; 1.0677x over previous
#include <cuda_runtime.h>
#include <cstdint>

// Problem constants (fixed by the dataset)
#define B_   16
#define S_   2048
#define D_   1024
#define P_   8192
#define R_   16

#define LCH  32               // rows per chunk == MAX_SPAN (load-bearing!)
#define NCH  (S_ / LCH)       // 64 chunks
#define OUTW (2 * D_ + R_)    // 2064 floats per output row

// arr[b][s][d]: inclusive prefix of tok within the chunk containing s (only flagged rows valid)
__device__ float g_arr[(size_t)B_ * S_ * D_];            // ~134 MB
__device__ float g_part[(size_t)B_ * NCH * D_];          // chunk totals (4 MB, L2-resident)
__device__ int   g_flag[(B_ * S_) / 4];                  // packed byte flags (8K ints)

// ---------------------------------------------------------------------------
// Zero the flag array (device globals persist across graph replays).
__global__ void k_init_flags() {
    int i = blockIdx.x * blockDim.x + threadIdx.x;
    if (i < (B_ * S_) / 4) g_flag[i] = 0;
}

// Mark rows of arr that k_pairs will read: for endpoint e>0, row (e-1) of batch b.
__global__ void k_mark(const int* __restrict__ batch_idx,
                       const int* __restrict__ e1s, const int* __restrict__ e1e,
                       const int* __restrict__ e2s, const int* __restrict__ e2e) {
    int i = blockIdx.x * blockDim.x + threadIdx.x;      // [0, 4P)
    if (i >= 4 * P_) return;
    int p = i & (P_ - 1);
    int which = i >> 13;                                 // P = 8192 = 2^13
    int e;
    switch (which) {
        case 0: e = e1s[p]; break;
        case 1: e = e1e[p]; break;
        case 2: e = e2s[p]; break;
        default: e = e2e[p]; break;
    }
    if (e > 0) ((unsigned char*)g_flag)[batch_idx[p] * S_ + (e - 1)] = 1;
}

// ---------------------------------------------------------------------------
// Single tok pass: per (b, chunk, d4) running prefix; write only flagged rows;
// emit chunk total unconditionally.
__global__ void k_local_prefix(const float* __restrict__ tok) {
    __shared__ unsigned char sflag[LCH];
    int idx = blockIdx.x * blockDim.x + threadIdx.x;
    int d4   = idx & (D_ / 4 - 1);
    int rest = idx >> 8;                                  // D/4 = 256
    int ch   = rest & (NCH - 1);
    int b    = rest >> 6;                                 // NCH = 64

    if (threadIdx.x < LCH)
        sflag[threadIdx.x] = ((const unsigned char*)g_flag)[b * S_ + ch * LCH + threadIdx.x];
    __syncthreads();

    const float4* t  = (const float4*)(tok   + ((size_t)b * S_ + (size_t)ch * LCH) * D_) + d4;
    float4*       ar = (float4*)      (g_arr + ((size_t)b * S_ + (size_t)ch * LCH) * D_) + d4;

    float4 run = make_float4(0.f, 0.f, 0.f, 0.f);
#pragma unroll
    for (int i = 0; i < LCH; ++i) {
        float4 v = t[(size_t)i * (D_ / 4)];
        run.x += v.x; run.y += v.y; run.z += v.z; run.w += v.w;
        if (sflag[i]) ar[(size_t)i * (D_ / 4)] = run;
    }
    ((float4*)(g_part + ((size_t)b * NCH + ch) * D_))[d4] = run;
}

// ---------------------------------------------------------------------------
// Span numerator without any global base: span <= LCH means endpoints are in
// the same or adjacent chunks:
//   s == 0           : cs[e] = arr[e-1]                     (chunk 0, base 0)
//   same chunk       : cs[e]-cs[s] = arr[e-1] - arr[s-1]
//   adjacent chunks  : cs[e]-cs[s] = arr[e-1] - arr[s-1] + part[chunk(s-1)]
__device__ __forceinline__ float4 span_num(const float4* arr_b, const float4* part_b,
                                           int s, int f, int t) {
    float4 hi = arr_b[(size_t)(f - 1) * (D_ / 4) + t];
    float4 r = hi;
    if (s > 0) {
        float4 lo = arr_b[(size_t)(s - 1) * (D_ / 4) + t];
        r.x -= lo.x; r.y -= lo.y; r.z -= lo.z; r.w -= lo.w;
        int cbs = (s - 1) >> 5;                 // LCH = 32
        int cbf = (f - 1) >> 5;
        if (cbf != cbs) {
            float4 br = part_b[(size_t)cbs * (D_ / 4) + t];
            r.x += br.x; r.y += br.y; r.z += br.z; r.w += br.w;
        }
    }
    return r;
}

__global__ void k_pairs(const int* __restrict__ batch_idx,
                        const int* __restrict__ e1s, const int* __restrict__ e1e,
                        const int* __restrict__ e2s, const int* __restrict__ e2e,
                        const int* __restrict__ rel_idx,
                        const float* __restrict__ rel_table,
                        float* __restrict__ out) {
    int p = blockIdx.x;
    int t = threadIdx.x;

    int b  = __ldg(batch_idx + p);
    int s1 = __ldg(e1s + p), f1 = __ldg(e1e + p);
    int s2 = __ldg(e2s + p), f2 = __ldg(e2e + p);

    const float4* arr_b  = (const float4*)(g_arr  + (size_t)b * S_ * D_);
    const float4* part_b = (const float4*)(g_part + (size_t)b * NCH * D_);
    float4* orow = (float4*)(out + (size_t)p * OUTW);

    float inv1 = 1.0f / (float)(f1 - s1);
    float inv2 = 1.0f / (float)(f2 - s2);

    float4 n1 = span_num(arr_b, part_b, s1, f1, t);
    orow[t] = make_float4(n1.x * inv1, n1.y * inv1, n1.z * inv1, n1.w * inv1);

    float4 n2 = span_num(arr_b, part_b, s2, f2, t);
    orow[D_ / 4 + t] = make_float4(n2.x * inv2, n2.y * inv2, n2.z * inv2, n2.w * inv2);

    if (t < R_) {
        int ri = __ldg(rel_idx + p);
        out[(size_t)p * OUTW + 2 * D_ + t] = __ldg(rel_table + (size_t)ri * R_ + t);
    }
}

// ---------------------------------------------------------------------------
extern "C" void kernel_launch(void* const* d_in, const int* in_sizes, int n_in,
                              void* d_out, int out_size) {
    const float* tok       = (const float*)d_in[0];
    const int*   batch_idx = (const int*)d_in[1];
    const int*   e1s       = (const int*)d_in[2];
    const int*   e1e       = (const int*)d_in[3];
    const int*   e2s       = (const int*)d_in[4];
    const int*   e2e       = (const int*)d_in[5];
    const int*   rel_idx   = (const int*)d_in[6];
    const float* rel_table = (const float*)d_in[7];
    float* out = (float*)d_out;

    (void)in_sizes; (void)n_in; (void)out_size;

    k_init_flags<<<(B_ * S_ / 4 + 255) / 256, 256>>>();
    k_mark<<<(4 * P_) / 256, 256>>>(batch_idx, e1s, e1e, e2s, e2e);
    k_local_prefix<<<B_ * NCH * (D_ / 4) / 256, 256>>>(tok);
    k_pairs<<<P_, 256>>>(batch_idx, e1s, e1e, e2s, e2e, rel_idx, rel_table, out);
}

// round 5
// speedup vs baseline: 1.5598x; 1.1799x over previous
#include <cuda_runtime.h>
#include <cstdint>

// Problem constants (fixed by the dataset)
#define B_   16
#define S_   2048
#define D_   1024
#define P_   8192
#define R_   16

#define LCH  32               // rows per chunk == MAX_SPAN (load-bearing!)
#define NCH  (S_ / LCH)       // 64 chunks
#define OUTW (2 * D_ + R_)    // 2064 floats per output row

#define PAIRS_PER_BLK 2

// arr[b][s][d]: inclusive prefix of tok within the chunk containing s (only flagged rows valid)
__device__ float g_arr[(size_t)B_ * S_ * D_];            // ~134 MB address space, ~83 MB touched
__device__ float g_part[(size_t)B_ * NCH * D_];          // chunk totals (4 MB, L2-resident)
__device__ int   g_flag[(B_ * S_) / 4];                  // packed byte flags (8K ints)

// ---------------------------------------------------------------------------
__global__ void k_init_flags() {
    int i = blockIdx.x * blockDim.x + threadIdx.x;
    if (i < (B_ * S_) / 4) g_flag[i] = 0;
}

// Mark rows of arr that k_pairs will read: for endpoint e>0, row (e-1) of batch b.
__global__ void k_mark(const int* __restrict__ batch_idx,
                       const int* __restrict__ e1s, const int* __restrict__ e1e,
                       const int* __restrict__ e2s, const int* __restrict__ e2e) {
    int i = blockIdx.x * blockDim.x + threadIdx.x;      // [0, 4P)
    if (i >= 4 * P_) return;
    int p = i & (P_ - 1);
    int which = i >> 13;                                 // P = 8192 = 2^13
    int e;
    switch (which) {
        case 0: e = e1s[p]; break;
        case 1: e = e1e[p]; break;
        case 2: e = e2s[p]; break;
        default: e = e2e[p]; break;
    }
    if (e > 0) ((unsigned char*)g_flag)[batch_idx[p] * S_ + (e - 1)] = 1;
}

// ---------------------------------------------------------------------------
// Single tok pass: per (b, chunk, d4) running prefix; write only flagged rows;
// emit chunk total unconditionally. tok is read ONCE -> streaming loads (.cs)
// so the arr/part writes stay L2-resident for k_pairs.
__global__ void k_local_prefix(const float* __restrict__ tok) {
    __shared__ unsigned char sflag[LCH];
    int idx = blockIdx.x * blockDim.x + threadIdx.x;
    int d4   = idx & (D_ / 4 - 1);
    int rest = idx >> 8;                                  // D/4 = 256
    int ch   = rest & (NCH - 1);
    int b    = rest >> 6;                                 // NCH = 64

    if (threadIdx.x < LCH)
        sflag[threadIdx.x] = ((const unsigned char*)g_flag)[b * S_ + ch * LCH + threadIdx.x];
    __syncthreads();

    const float4* t  = (const float4*)(tok   + ((size_t)b * S_ + (size_t)ch * LCH) * D_) + d4;
    float4*       ar = (float4*)      (g_arr + ((size_t)b * S_ + (size_t)ch * LCH) * D_) + d4;

    float4 run = make_float4(0.f, 0.f, 0.f, 0.f);
#pragma unroll
    for (int i = 0; i < LCH; ++i) {
        float4 v = __ldcs(t + (size_t)i * (D_ / 4));     // streaming read
        run.x += v.x; run.y += v.y; run.z += v.z; run.w += v.w;
        if (sflag[i]) ar[(size_t)i * (D_ / 4)] = run;    // keep in L2
    }
    ((float4*)(g_part + ((size_t)b * NCH + ch) * D_))[d4] = run;
}

// ---------------------------------------------------------------------------
// Span numerator: span <= LCH means endpoints are in same or adjacent chunks:
//   s == 0           : cs[e] = arr[e-1]
//   same chunk       : cs[e]-cs[s] = arr[e-1] - arr[s-1]
//   adjacent chunks  : cs[e]-cs[s] = arr[e-1] - arr[s-1] + part[chunk(s-1)]
__device__ __forceinline__ float4 span_num(const float4* arr_b, const float4* part_b,
                                           int s, int f, int t) {
    float4 r = arr_b[(size_t)(f - 1) * (D_ / 4) + t];
    if (s > 0) {
        float4 lo = arr_b[(size_t)(s - 1) * (D_ / 4) + t];
        r.x -= lo.x; r.y -= lo.y; r.z -= lo.z; r.w -= lo.w;
        int cbs = (s - 1) >> 5;                 // LCH = 32
        int cbf = (f - 1) >> 5;
        if (cbf != cbs) {
            float4 br = part_b[(size_t)cbs * (D_ / 4) + t];
            r.x += br.x; r.y += br.y; r.z += br.z; r.w += br.w;
        }
    }
    return r;
}

// 512 threads = 2 pairs per block; out written with streaming stores so arr
// stays L2-resident throughout.
__global__ void k_pairs(const int* __restrict__ batch_idx,
                        const int* __restrict__ e1s, const int* __restrict__ e1e,
                        const int* __restrict__ e2s, const int* __restrict__ e2e,
                        const int* __restrict__ rel_idx,
                        const float* __restrict__ rel_table,
                        float* __restrict__ out) {
    int p = blockIdx.x * PAIRS_PER_BLK + (threadIdx.x >> 8);
    int t = threadIdx.x & 255;          // float4 lane

    int b  = __ldg(batch_idx + p);
    int s1 = __ldg(e1s + p), f1 = __ldg(e1e + p);
    int s2 = __ldg(e2s + p), f2 = __ldg(e2e + p);

    const float4* arr_b  = (const float4*)(g_arr  + (size_t)b * S_ * D_);
    const float4* part_b = (const float4*)(g_part + (size_t)b * NCH * D_);
    float4* orow = (float4*)(out + (size_t)p * OUTW);

    float inv1 = 1.0f / (float)(f1 - s1);
    float inv2 = 1.0f / (float)(f2 - s2);

    float4 n1 = span_num(arr_b, part_b, s1, f1, t);
    __stcs(orow + t, make_float4(n1.x * inv1, n1.y * inv1, n1.z * inv1, n1.w * inv1));

    float4 n2 = span_num(arr_b, part_b, s2, f2, t);
    __stcs(orow + D_ / 4 + t,
           make_float4(n2.x * inv2, n2.y * inv2, n2.z * inv2, n2.w * inv2));

    if (t < R_) {
        int ri = __ldg(rel_idx + p);
        __stcs(out + (size_t)p * OUTW + 2 * D_ + t,
               __ldg(rel_table + (size_t)ri * R_ + t));
    }
}

// ---------------------------------------------------------------------------
extern "C" void kernel_launch(void* const* d_in, const int* in_sizes, int n_in,
                              void* d_out, int out_size) {
    const float* tok       = (const float*)d_in[0];
    const int*   batch_idx = (const int*)d_in[1];
    const int*   e1s       = (const int*)d_in[2];
    const int*   e1e       = (const int*)d_in[3];
    const int*   e2s       = (const int*)d_in[4];
    const int*   e2e       = (const int*)d_in[5];
    const int*   rel_idx   = (const int*)d_in[6];
    const float* rel_table = (const float*)d_in[7];
    float* out = (float*)d_out;

    (void)in_sizes; (void)n_in; (void)out_size;

    k_init_flags<<<(B_ * S_ / 4 + 255) / 256, 256>>>();
    k_mark<<<(4 * P_) / 256, 256>>>(batch_idx, e1s, e1e, e2s, e2e);
    k_local_prefix<<<B_ * NCH * (D_ / 4) / 256, 256>>>(tok);
    k_pairs<<<P_ / PAIRS_PER_BLK, 256 * PAIRS_PER_BLK>>>(batch_idx, e1s, e1e, e2s, e2e,
                                                         rel_idx, rel_table, out);
}